// round 3
// baseline (speedup 1.0000x reference)
#include <cuda_runtime.h>
#include <cstdint>

// Problem constants
#define B_SZ  8
#define L_SZ  256
#define D1    512
#define D2    512
#define KOUT  64

typedef unsigned long long u64;

// Scratch for stage-1 result: tmp[b][i][k][q]  (8*256*64*512 fp32 = 256 MiB)
// Static __device__ array: allowed (no cudaMalloc anywhere).
__device__ float g_tmp[(size_t)B_SZ * L_SZ * KOUT * D2];

// ---------------------------------------------------------------------------
// Packed fp32x2 helpers (sm_100+ PTX). FFMA2 doubles fp32 FMA lanes per issue.
// ---------------------------------------------------------------------------
__device__ __forceinline__ u64 pack2(float lo, float hi) {
    u64 r;
    asm("mov.b64 %0, {%1, %2};" : "=l"(r) : "f"(lo), "f"(hi));
    return r;
}
__device__ __forceinline__ void unpack2(u64 v, float& lo, float& hi) {
    asm("mov.b64 {%0, %1}, %2;" : "=f"(lo), "=f"(hi) : "l"(v));
}
__device__ __forceinline__ void fma2(u64& d, u64 a, u64 b) {
    asm("fma.rn.f32x2 %0, %1, %2, %0;" : "+l"(d) : "l"(a), "l"(b));
}

// Inner microkernel: one p-slice.
// A fragment: 8 floats (rows u), duplicated into packed lanes.
// B fragment: 4 u64 loaded DIRECTLY from smem (adjacent float pairs) — no packs.
// acc[u][v] packs (C[u][2v], C[u][2v+1]).
__device__ __forceinline__ void micro_fma(const float* __restrict__ as_row,
                                          const float* __restrict__ bs_row,
                                          int tx, int ty,
                                          u64 acc[8][4]) {
    float af[8];
    *(float4*)&af[0] = *(const float4*)&as_row[ty * 8];
    *(float4*)&af[4] = *(const float4*)&as_row[ty * 8 + 4];
    u64 b2[4];
    {
        const u64* bp = (const u64*)&bs_row[tx * 8];   // 32B-aligned
        b2[0] = bp[0]; b2[1] = bp[1]; b2[2] = bp[2]; b2[3] = bp[3];
    }
#pragma unroll
    for (int u = 0; u < 8; ++u) {
        u64 a2 = pack2(af[u], af[u]);
#pragma unroll
        for (int v = 0; v < 4; ++v) fma2(acc[u][v], a2, b2[v]);
    }
}

// ---------------------------------------------------------------------------
// Stage 1:  tmp[b,i,k,q] = sum_p x1[b,i,p] * W[k,p,q]
// Per CTA: 128(i) x 128(q) tile of the (b,k) GEMM.  NN layout: A row-major
// [i,p], B row-major [p,q].  Double-buffered smem, 1 barrier per k-step.
// grid = (D2/128, L/128, B*KOUT)
// ---------------------------------------------------------------------------
__global__ __launch_bounds__(256)
void bilinear_stage1(const float* __restrict__ x1, const float* __restrict__ W) {
    const int t  = threadIdx.x;
    const int tx = t & 15;
    const int ty = t >> 4;

    const int bk = blockIdx.z;
    const int b  = bk >> 6;       // / KOUT
    const int k  = bk & 63;
    const int i0 = blockIdx.y * 128;
    const int q0 = blockIdx.x * 128;

    const float* A  = x1 + (size_t)b * L_SZ * D1;   // [256,512]
    const float* Bm = W  + (size_t)k * D1 * D2;     // [512,512]

    __shared__ float As[2][8][132];   // As[buf][p][i] (transposed store, pad 132)
    __shared__ float Bs[2][8][128];   // Bs[buf][p][q] (direct store)

    // A tile load map: 128 rows x 8 p, one float4/thread, stored transposed.
    const int a_row = t >> 1;
    const int a_seg = (t & 1) << 2;
    // B tile load map: 8 p x 128 q, one float4/thread, stored direct.
    const int b_p = t >> 5;
    const int b_q = (t & 31) << 2;

    u64 acc[8][4];
#pragma unroll
    for (int u = 0; u < 8; ++u)
#pragma unroll
        for (int v = 0; v < 4; ++v) acc[u][v] = 0ull;

    const float* a_ptr = A  + (size_t)(i0 + a_row) * D1 + a_seg;
    const float* b_ptr = Bm + (size_t)b_p * D2 + q0 + b_q;

    float4 av = *(const float4*)(a_ptr);
    float4 bv = *(const float4*)(b_ptr);

    int buf = 0;
    As[0][a_seg + 0][a_row] = av.x;
    As[0][a_seg + 1][a_row] = av.y;
    As[0][a_seg + 2][a_row] = av.z;
    As[0][a_seg + 3][a_row] = av.w;
    *(float4*)&Bs[0][b_p][b_q] = bv;
    __syncthreads();

    for (int p0 = 0; p0 < D1; p0 += 8) {
        const bool more = (p0 + 8 < D1);
        if (more) {   // issue next-tile global loads before compute (latency hide)
            av = *(const float4*)(a_ptr + p0 + 8);
            bv = *(const float4*)(b_ptr + (size_t)(p0 + 8) * D2);
        }

#pragma unroll
        for (int p = 0; p < 8; ++p)
            micro_fma(&As[buf][p][0], &Bs[buf][p][0], tx, ty, acc);

        if (more) {
            const int nb = buf ^ 1;
            As[nb][a_seg + 0][a_row] = av.x;
            As[nb][a_seg + 1][a_row] = av.y;
            As[nb][a_seg + 2][a_row] = av.z;
            As[nb][a_seg + 3][a_row] = av.w;
            *(float4*)&Bs[nb][b_p][b_q] = bv;
            __syncthreads();
            buf = nb;
        }
    }

    float c[8][8];
#pragma unroll
    for (int u = 0; u < 8; ++u)
#pragma unroll
        for (int v = 0; v < 4; ++v) unpack2(acc[u][v], c[u][2 * v], c[u][2 * v + 1]);

#pragma unroll
    for (int u = 0; u < 8; ++u) {
        const int i = i0 + ty * 8 + u;
        float* dst = g_tmp + (((size_t)b * L_SZ + i) * KOUT + k) * D2 + q0 + tx * 8;
        *(float4*)(dst)     = make_float4(c[u][0], c[u][1], c[u][2], c[u][3]);
        *(float4*)(dst + 4) = make_float4(c[u][4], c[u][5], c[u][6], c[u][7]);
    }
}

// ---------------------------------------------------------------------------
// Stage 2:  out[b,i,j,k] = sum_q tmp[b,i,k,q] * x2[b,j,q] + bias[k]
// Per batch b this is an NT GEMM: rows r = i*64+k (M=16384), cols j (N=256),
// reduction over q (512).  Both operands row-major with contiguous q -> both
// loaded transposed into smem.  Double-buffered, 1 barrier per k-step.
// grid = (L/128, (L*KOUT)/128, B)
// ---------------------------------------------------------------------------
__global__ __launch_bounds__(256)
void bilinear_stage2(const float* __restrict__ x2, const float* __restrict__ bias,
                     float* __restrict__ out) {
    const int t  = threadIdx.x;
    const int tx = t & 15;
    const int ty = t >> 4;

    const int b  = blockIdx.z;
    const int r0 = blockIdx.y * 128;   // r = i*64 + k
    const int j0 = blockIdx.x * 128;

    const float* A  = g_tmp + (size_t)b * L_SZ * KOUT * D2;  // rows r: stride D2
    const float* Bm = x2    + (size_t)b * L_SZ * D2;         // rows j: stride D2

    __shared__ float As[2][8][132];   // As[buf][q][r]
    __shared__ float Bs[2][8][132];   // Bs[buf][q][j]

    const int a_row = t >> 1;
    const int a_seg = (t & 1) << 2;

    u64 acc[8][4];
#pragma unroll
    for (int u = 0; u < 8; ++u)
#pragma unroll
        for (int v = 0; v < 4; ++v) acc[u][v] = 0ull;

    const float* a_ptr = A  + (size_t)(r0 + a_row) * D2 + a_seg;
    const float* b_ptr = Bm + (size_t)(j0 + a_row) * D2 + a_seg;

    float4 av = *(const float4*)(a_ptr);
    float4 bv = *(const float4*)(b_ptr);

    int buf = 0;
    As[0][a_seg + 0][a_row] = av.x;
    As[0][a_seg + 1][a_row] = av.y;
    As[0][a_seg + 2][a_row] = av.z;
    As[0][a_seg + 3][a_row] = av.w;
    Bs[0][a_seg + 0][a_row] = bv.x;
    Bs[0][a_seg + 1][a_row] = bv.y;
    Bs[0][a_seg + 2][a_row] = bv.z;
    Bs[0][a_seg + 3][a_row] = bv.w;
    __syncthreads();

    for (int q0 = 0; q0 < D2; q0 += 8) {
        const bool more = (q0 + 8 < D2);
        if (more) {
            av = *(const float4*)(a_ptr + q0 + 8);
            bv = *(const float4*)(b_ptr + q0 + 8);
        }

#pragma unroll
        for (int p = 0; p < 8; ++p)
            micro_fma(&As[buf][p][0], &Bs[buf][p][0], tx, ty, acc);

        if (more) {
            const int nb = buf ^ 1;
            As[nb][a_seg + 0][a_row] = av.x;
            As[nb][a_seg + 1][a_row] = av.y;
            As[nb][a_seg + 2][a_row] = av.z;
            As[nb][a_seg + 3][a_row] = av.w;
            Bs[nb][a_seg + 0][a_row] = bv.x;
            Bs[nb][a_seg + 1][a_row] = bv.y;
            Bs[nb][a_seg + 2][a_row] = bv.z;
            Bs[nb][a_seg + 3][a_row] = bv.w;
            __syncthreads();
            buf = nb;
        }
    }

    float c[8][8];   // c[u = row(k) dim][v = col(j) dim]
#pragma unroll
    for (int u = 0; u < 8; ++u)
#pragma unroll
        for (int v = 0; v < 4; ++v) unpack2(acc[u][v], c[u][2 * v], c[u][2 * v + 1]);

    // Thread's 8 rows are 8 consecutive k within one i (128-row tiles and
    // 8-row thread strips both divide KOUT=64 cleanly, so never cross i).
    const int rbase = r0 + ty * 8;
    const int i  = rbase >> 6;
    const int k0 = rbase & 63;

    float bias8[8];
    *(float4*)&bias8[0] = *(const float4*)&bias[k0];
    *(float4*)&bias8[4] = *(const float4*)&bias[k0 + 4];

#pragma unroll
    for (int v = 0; v < 8; ++v) {
        const int j = j0 + tx * 8 + v;
        float* dst = out + (((size_t)b * L_SZ + i) * L_SZ + j) * KOUT + k0;
        *(float4*)(dst)     = make_float4(c[0][v] + bias8[0], c[1][v] + bias8[1],
                                          c[2][v] + bias8[2], c[3][v] + bias8[3]);
        *(float4*)(dst + 4) = make_float4(c[4][v] + bias8[4], c[5][v] + bias8[5],
                                          c[6][v] + bias8[6], c[7][v] + bias8[7]);
    }
}

// ---------------------------------------------------------------------------
// Launch: two kernels in stream order (graph-capturable, allocation-free).
// Inputs (metadata order): inputs1, inputs2, weight, bias.  Output fp32.
// ---------------------------------------------------------------------------
extern "C" void kernel_launch(void* const* d_in, const int* in_sizes, int n_in,
                              void* d_out, int out_size) {
    const float* x1   = (const float*)d_in[0];   // [8,256,512]
    const float* x2   = (const float*)d_in[1];   // [8,256,512]
    const float* W    = (const float*)d_in[2];   // [64,512,512]
    const float* bias = (const float*)d_in[3];   // [64]
    float* out = (float*)d_out;                  // [8,256,256,64]

    dim3 g1(D2 / 128, L_SZ / 128, B_SZ * KOUT);          // (4, 2, 512)
    bilinear_stage1<<<g1, 256>>>(x1, W);

    dim3 g2(L_SZ / 128, (L_SZ * KOUT) / 128, B_SZ);      // (2, 128, 8)
    bilinear_stage2<<<g2, 256>>>(x2, bias, out);
}